// round 1
// baseline (speedup 1.0000x reference)
#include <cuda_runtime.h>
#include <stdint.h>

// FieldAwareFM: B=16384 samples, F=10 fields, D=8 factor dim.
// Inputs (metadata order):
//   d_in[0] = x        (B*F)            int32   per-field raw indices
//   d_in[1] = w_linear (INPUT_DIM)      float32
//   d_in[2] = b_linear (1)              float32
//   d_in[3] = emb      (F*INPUT_DIM*D)  float32
// Output: (B,) float32
//
// out[b] = b_lin + sum_f w[idx_f] + sum_{f<g} <emb[f][idx_g], emb[g][idx_f]>

#define BATCH      16384
#define NUM_FIELDS 10
#define FACTOR_DIM 8
#define INPUT_DIM  188610
#define NUM_PAIRS  45

__constant__ int c_offsets[NUM_FIELDS] = {
    0, 100000, 150000, 170000, 180000, 185000, 187000, 188000, 188500, 188600
};

// pair p -> (f, g), f < g
__constant__ signed char c_pf[NUM_PAIRS] = {
    0,0,0,0,0,0,0,0,0,
    1,1,1,1,1,1,1,1,
    2,2,2,2,2,2,2,
    3,3,3,3,3,3,
    4,4,4,4,4,
    5,5,5,5,
    6,6,6,
    7,7,
    8
};
__constant__ signed char c_pg[NUM_PAIRS] = {
    1,2,3,4,5,6,7,8,9,
    2,3,4,5,6,7,8,9,
    3,4,5,6,7,8,9,
    4,5,6,7,8,9,
    5,6,7,8,9,
    6,7,8,9,
    7,8,9,
    8,9,
    9
};

__global__ __launch_bounds__(256)
void ffm_kernel(const int* __restrict__ x,
                const float* __restrict__ w,
                const float* __restrict__ b_lin,
                const float* __restrict__ emb,
                float* __restrict__ out)
{
    const int warp_in_block = threadIdx.x >> 5;
    const int lane          = threadIdx.x & 31;
    const int b             = blockIdx.x * (blockDim.x >> 5) + warp_in_block;
    if (b >= BATCH) return;

    // lanes 0..9 load this sample's indices (coalesced 40B), add field offsets
    int my_idx = 0;
    if (lane < NUM_FIELDS) {
        my_idx = x[b * NUM_FIELDS + lane] + c_offsets[lane];
    }

    // broadcast all 10 global indices to every lane
    int idxs[NUM_FIELDS];
#pragma unroll
    for (int g = 0; g < NUM_FIELDS; g++) {
        idxs[g] = __shfl_sync(0xffffffffu, my_idx, g);
    }

    float acc = 0.0f;

    // linear term: lanes 0..9 gather w[idx]
    if (lane < NUM_FIELDS) {
        acc = __ldg(&w[my_idx]);
    }

    // FFM pairs: lane handles pair lane and lane+32 (45 pairs total)
#pragma unroll 2
    for (int p = lane; p < NUM_PAIRS; p += 32) {
        const int f = (int)c_pf[p];
        const int g = (int)c_pg[p];
        // emb row: emb[f][idx][0..7], 32B aligned
        const float4* __restrict__ a =
            (const float4*)(emb + ((size_t)f * INPUT_DIM + (size_t)idxs[g]) * FACTOR_DIM);
        const float4* __restrict__ c =
            (const float4*)(emb + ((size_t)g * INPUT_DIM + (size_t)idxs[f]) * FACTOR_DIM);
        float4 a0 = __ldg(&a[0]);
        float4 a1 = __ldg(&a[1]);
        float4 c0 = __ldg(&c[0]);
        float4 c1 = __ldg(&c[1]);
        acc += a0.x * c0.x + a0.y * c0.y + a0.z * c0.z + a0.w * c0.w
             + a1.x * c1.x + a1.y * c1.y + a1.z * c1.z + a1.w * c1.w;
    }

    // warp reduction
#pragma unroll
    for (int off = 16; off > 0; off >>= 1) {
        acc += __shfl_xor_sync(0xffffffffu, acc, off);
    }

    if (lane == 0) {
        out[b] = acc + __ldg(&b_lin[0]);
    }
}

extern "C" void kernel_launch(void* const* d_in, const int* in_sizes, int n_in,
                              void* d_out, int out_size)
{
    (void)in_sizes; (void)n_in; (void)out_size;
    const int*   x     = (const int*)d_in[0];
    const float* w     = (const float*)d_in[1];
    const float* b_lin = (const float*)d_in[2];
    const float* emb   = (const float*)d_in[3];
    float*       out   = (float*)d_out;

    const int warps_per_block = 8;            // 256 threads
    const int blocks = BATCH / warps_per_block; // 2048
    ffm_kernel<<<blocks, warps_per_block * 32>>>(x, w, b_lin, emb, out);
}